// round 1
// baseline (speedup 1.0000x reference)
#include <cuda_runtime.h>
#include <math.h>

// ---------------- static device scratch (no allocation allowed) ----------------
#define BS 16
#define C  64
#define H  128
#define W  128
#define EXP 4
#define HID 16
#define KK 9           // 3x3
#define WPERO 576      // 64*9 weights per (b,o)

__device__ float g_pooled[BS * C];                 // [b][c]
__device__ float g_coeff[BS * C * EXP];            // [b][c][e]
__device__ float g_aw1[BS * C * C * KK];           // [b][o][i][kk]
__device__ float g_aw2[BS * C * C * KK];
__device__ float g_aw3[BS * C * C * KK];
__device__ float g_ab[3 * BS * C];                 // [layer][b][c]
__device__ float g_buf1[BS * C * H * W];
__device__ float g_buf2[BS * C * H * W];

// ---------------- kernel A: global average pool ----------------
__global__ void pool_kernel(const float* __restrict__ x) {
    int bc = blockIdx.x;                           // 0..1023
    const float4* p = (const float4*)(x + (size_t)bc * (H * W));
    float s = 0.f;
    for (int i = threadIdx.x; i < (H * W) / 4; i += 256) {
        float4 v = p[i];
        s += (v.x + v.y) + (v.z + v.w);
    }
    __shared__ float sm[256];
    sm[threadIdx.x] = s;
    __syncthreads();
    for (int st = 128; st > 0; st >>= 1) {
        if (threadIdx.x < st) sm[threadIdx.x] += sm[threadIdx.x + st];
        __syncthreads();
    }
    if (threadIdx.x == 0) g_pooled[bc] = sm[0] * (1.0f / (H * W));
}

// ---------------- kernel B: control MLP + softmax + bias mixing ----------------
__global__ void ctrl_kernel(const float* __restrict__ w1,   // [HID, C]
                            const float* __restrict__ w2,   // [E*C, HID]
                            const float* __restrict__ b1,   // [E, C]
                            const float* __restrict__ b2,
                            const float* __restrict__ b3) {
    __shared__ float sp[BS * C];        // pooled
    __shared__ float sh[BS * HID];      // hidden
    __shared__ float sl[BS * EXP * C];  // logits [b][j]
    int t = threadIdx.x;                // 256 threads

    for (int i = t; i < BS * C; i += 256) sp[i] = g_pooled[i];
    __syncthreads();

    // hidden: 256 entries, one per thread
    {
        int b = t / HID, hh = t % HID;
        float s = 0.f;
        #pragma unroll 8
        for (int c = 0; c < C; c++) s += sp[b * C + c] * w1[hh * C + c];
        sh[b * HID + hh] = fmaxf(s, 0.f);
    }
    __syncthreads();

    // logits: thread t owns column j=t for all b
    for (int b = 0; b < BS; b++) {
        float s = 0.f;
        #pragma unroll
        for (int h = 0; h < HID; h++) s += sh[b * HID + h] * w2[t * HID + h];
        sl[b * (EXP * C) + t] = s;
    }
    __syncthreads();

    // softmax over E=4 per (b,c), temperature 30
    for (int g = t; g < BS * C; g += 256) {
        int b = g / C, c = g % C;
        float v[EXP];
        float mx = -1e30f;
        #pragma unroll
        for (int e = 0; e < EXP; e++) {
            v[e] = sl[b * (EXP * C) + c * EXP + e] * (1.0f / 30.0f);
            mx = fmaxf(mx, v[e]);
        }
        float den = 0.f;
        #pragma unroll
        for (int e = 0; e < EXP; e++) { v[e] = expf(v[e] - mx); den += v[e]; }
        float inv = 1.0f / den;
        #pragma unroll
        for (int e = 0; e < EXP; e++) g_coeff[g * EXP + e] = v[e] * inv;
    }
    __syncthreads();

    // mixed biases for all 3 layers
    for (int g = t; g < BS * C; g += 256) {
        int c = g % C;
        float c0 = g_coeff[g * EXP + 0], c1 = g_coeff[g * EXP + 1];
        float c2 = g_coeff[g * EXP + 2], c3 = g_coeff[g * EXP + 3];
        g_ab[0 * BS * C + g] = c0 * b1[0 * C + c] + c1 * b1[1 * C + c] + c2 * b1[2 * C + c] + c3 * b1[3 * C + c];
        g_ab[1 * BS * C + g] = c0 * b2[0 * C + c] + c1 * b2[1 * C + c] + c2 * b2[2 * C + c] + c3 * b2[3 * C + c];
        g_ab[2 * BS * C + g] = c0 * b3[0 * C + c] + c1 * b3[1 * C + c] + c2 * b3[2 * C + c] + c3 * b3[3 * C + c];
    }
}

// ---------------- kernel C: per-sample weight mixing ----------------
// AW[b][o][i][kk] = sum_e coeff[b][o][e] * W[e][o][i][kk]
__global__ void mixw_kernel(const float* __restrict__ Wt, float* __restrict__ AW) {
    int idx = blockIdx.x * 256 + threadIdx.x;
    if (idx >= BS * C * WPERO) return;
    int rest = idx % WPERO;               // i*9+kk
    int o = (idx / WPERO) % C;
    int b = idx / (WPERO * C);
    const float* cf = &g_coeff[(b * C + o) * EXP];
    float s = 0.f;
    #pragma unroll
    for (int e = 0; e < EXP; e++)
        s += cf[e] * Wt[((size_t)e * C + o) * WPERO + rest];
    AW[idx] = s;
}

// ---------------- kernel D: direct 3x3 conv, per-sample weights ----------------
// block: b = blockIdx.z, o-group (8) = blockIdx.y, 32x32 spatial tile = blockIdx.x
// thread: ty = t/8 (row 0..31), txg = t%8 -> 4 contiguous columns
#define TSTRIDE 35
__global__ __launch_bounds__(256, 2)
void conv_kernel(const float* __restrict__ in, const float* __restrict__ aw,
                 const float* __restrict__ ab, float* __restrict__ out) {
    const int b    = blockIdx.z;
    const int ob   = blockIdx.y * 8;
    const int tile = blockIdx.x;
    const int ty0  = (tile / 4) * 32;
    const int tx0  = (tile % 4) * 32;
    const int t    = threadIdx.x;
    const int ty   = t / 8;
    const int tx   = (t % 8) * 4;

    __shared__ float sin_[8][34][TSTRIDE];
    __shared__ float sw_[8 * KK * 8];     // [ci][kk][o], o contiguous

    float acc[8][4];
    #pragma unroll
    for (int o = 0; o < 8; o++)
        #pragma unroll
        for (int p = 0; p < 4; p++) acc[o][p] = 0.f;

    const float* inb = in + (size_t)b * C * H * W;
    const float* awb = aw + ((size_t)b * C + ob) * WPERO;

    for (int ci0 = 0; ci0 < C; ci0 += 8) {
        // ---- stage input tile (34x34 halo) for 8 channels ----
        for (int i = t; i < 8 * 34 * 34; i += 256) {
            int c   = i / 1156;
            int rem = i % 1156;
            int r   = rem / 34;
            int col = rem % 34;
            int gy = ty0 - 1 + r;
            int gx = tx0 - 1 + col;
            float v = 0.f;
            if (gy >= 0 && gy < H && gx >= 0 && gx < W)
                v = inb[(size_t)(ci0 + c) * (H * W) + gy * W + gx];
            sin_[c][r][col] = v;
        }
        // ---- stage weights: sw_[(c*9+kk)*8+o] = aw[b][ob+o][ci0+c][kk] ----
        for (int i = t; i < 576; i += 256) {
            int o  = i % 8;
            int kk = (i / 8) % KK;
            int c  = i / (8 * KK);
            sw_[i] = awb[(size_t)o * WPERO + (ci0 + c) * KK + kk];
        }
        __syncthreads();

        #pragma unroll
        for (int c = 0; c < 8; c++) {
            #pragma unroll
            for (int ky = 0; ky < 3; ky++) {
                float in6[6];
                #pragma unroll
                for (int q = 0; q < 6; q++) in6[q] = sin_[c][ty + ky][tx + q];
                #pragma unroll
                for (int kx = 0; kx < 3; kx++) {
                    const float4 wa = *(const float4*)&sw_[(c * KK + ky * 3 + kx) * 8];
                    const float4 wb = *(const float4*)&sw_[(c * KK + ky * 3 + kx) * 8 + 4];
                    float wv[8] = {wa.x, wa.y, wa.z, wa.w, wb.x, wb.y, wb.z, wb.w};
                    #pragma unroll
                    for (int o = 0; o < 8; o++) {
                        #pragma unroll
                        for (int p = 0; p < 4; p++)
                            acc[o][p] = fmaf(in6[p + kx], wv[o], acc[o][p]);
                    }
                }
            }
        }
        __syncthreads();
    }

    // ---- epilogue: add bias, vectorized store ----
    const int oy = ty0 + ty;
    const int ox = tx0 + tx;
    float* outb = out + ((size_t)b * C + ob) * (H * W);
    #pragma unroll
    for (int o = 0; o < 8; o++) {
        float bias = ab[b * C + ob + o];
        float4 v = make_float4(acc[o][0] + bias, acc[o][1] + bias,
                               acc[o][2] + bias, acc[o][3] + bias);
        *(float4*)&outb[(size_t)o * (H * W) + oy * W + ox] = v;
    }
}

// ---------------- launch ----------------
extern "C" void kernel_launch(void* const* d_in, const int* in_sizes, int n_in,
                              void* d_out, int out_size) {
    (void)in_sizes; (void)n_in; (void)out_size;
    const float* x       = (const float*)d_in[0];
    const float* w_ctrl1 = (const float*)d_in[1];
    const float* w_ctrl2 = (const float*)d_in[2];
    const float* weight1 = (const float*)d_in[3];
    const float* weight2 = (const float*)d_in[4];
    const float* weight3 = (const float*)d_in[5];
    const float* bias1   = (const float*)d_in[6];
    const float* bias2   = (const float*)d_in[7];
    const float* bias3   = (const float*)d_in[8];
    float* out = (float*)d_out;

    float *aw1, *aw2, *aw3, *ab, *buf1, *buf2;
    cudaGetSymbolAddress((void**)&aw1,  g_aw1);
    cudaGetSymbolAddress((void**)&aw2,  g_aw2);
    cudaGetSymbolAddress((void**)&aw3,  g_aw3);
    cudaGetSymbolAddress((void**)&ab,   g_ab);
    cudaGetSymbolAddress((void**)&buf1, g_buf1);
    cudaGetSymbolAddress((void**)&buf2, g_buf2);

    pool_kernel<<<BS * C, 256>>>(x);
    ctrl_kernel<<<1, 256>>>(w_ctrl1, w_ctrl2, bias1, bias2, bias3);

    const int mix_total = BS * C * WPERO;           // 589824
    mixw_kernel<<<mix_total / 256, 256>>>(weight1, aw1);
    mixw_kernel<<<mix_total / 256, 256>>>(weight2, aw2);
    mixw_kernel<<<mix_total / 256, 256>>>(weight3, aw3);

    dim3 grid(16, 8, BS);                            // spatial tiles, o-groups, batch
    conv_kernel<<<grid, 256>>>(x,    aw1, ab + 0 * BS * C, buf1);
    conv_kernel<<<grid, 256>>>(buf1, aw2, ab + 1 * BS * C, buf2);
    conv_kernel<<<grid, 256>>>(buf2, aw3, ab + 2 * BS * C, out);
}